// round 15
// baseline (speedup 1.0000x reference)
#include <cuda_runtime.h>
#include <cuda_bf16.h>
#include <math.h>
#include <stdint.h>

#define ALPHA 0.01f
#define BATCH 65536

// ---------------- device scratch (no runtime allocation allowed) ----------------
__device__ float g_y1[65536 * 256];
__device__ float g_y2[65536 * 128];
__device__ float g_y3[65536 * 128];
__device__ float g_y4[65536 * 128];
__device__ float g_y5[65536 * 32];
__device__ double g_part[5 * 1024];
__device__ float g_clog[257];   // c * log(c)
__device__ float g_logt[257];   // log(c)

// ---------------- helpers ----------------
__device__ __forceinline__ uint32_t smem_u32(const void* p) {
    uint32_t a;
    asm("{ .reg .u64 t; cvta.to.shared.u64 t, %1; cvt.u32.u64 %0, t; }" : "=r"(a) : "l"(p));
    return a;
}
__device__ __forceinline__ void ldmatrix_x4(uint32_t* r, uint32_t addr) {
    asm volatile("ldmatrix.sync.aligned.m8n8.x4.shared.b16 {%0,%1,%2,%3}, [%4];"
                 : "=r"(r[0]), "=r"(r[1]), "=r"(r[2]), "=r"(r[3]) : "r"(addr));
}
__device__ __forceinline__ void mma_bf16(float* c, const uint32_t* a, uint32_t b0, uint32_t b1) {
    asm volatile(
        "mma.sync.aligned.m16n8k16.row.col.f32.bf16.bf16.f32 "
        "{%0,%1,%2,%3}, {%4,%5,%6,%7}, {%8,%9}, {%0,%1,%2,%3};"
        : "+f"(c[0]), "+f"(c[1]), "+f"(c[2]), "+f"(c[3])
        : "r"(a[0]), "r"(a[1]), "r"(a[2]), "r"(a[3]), "r"(b0), "r"(b1));
}

// ============ HMMA GEMM: Y[M,NTOT] = leaky_relu(A[M,K] @ W[NTOT,K]^T + bias) ============
// bf16 hi/lo per row: bytes [0,64)=hi(32), [64,128)=lo(32), [128,144)=pad. 3 MMAs per 16-k:
// ah*bh + ah*bl + al*bh. BK=32 chunks (2 sub-steps, ONE barrier per 32-k), double-buffered
// dynamic SMEM (2 x 36KB stages). 128x128 CTA tile, 8 warps of 64x32 (proven R12 layout).
// K not multiple of 32 -> last chunk zero-padded (exact: zeros contribute nothing).
template <int NTOT, int K>
__global__ __launch_bounds__(256) void hmma_gemm_kernel(
    const float* __restrict__ A, const float* __restrict__ W,
    const float* __restrict__ bias, float* __restrict__ Y) {
    constexpr int NC = (K + 31) / 32;
    constexpr bool RAGGED = (K % 32) != 0;
    constexpr int ROWB = 144;                    // bytes per row (64 hi + 64 lo + 16 pad)
    constexpr int MATB = 128 * ROWB;             // 18432 B per matrix per stage
    constexpr int STAGEB = 2 * MATB;             // A + B
    extern __shared__ __align__(16) char dsm[];
    __shared__ float sBias[128];

    const int tid = threadIdx.x;
    const int lane = tid & 31;
    const int w = tid >> 5;
    const int wm = w & 1;                        // 2 warps along M (64 each)
    const int wn = w >> 1;                       // 4 warps along N (32 each)
    const long m0 = (long)blockIdx.y * 128;
    const int n0 = blockIdx.x * 128;

    if (tid < 128) sBias[tid] = bias[n0 + tid];

    // loader: i = tid + 256*r, r<4; row = i>>3 (0..127), cc = i&7 (float4 within 32 floats)
    const int ldRow = tid >> 3;                  // 0..31 (+32r)
    const int ldCc = tid & 7;

    float4 aReg[4], bReg[4];
    auto load_g = [&](int c) {
        int k = c * 32 + ldCc * 4;
#pragma unroll
        for (int r = 0; r < 4; r++) {
            int row = ldRow + r * 32;
            if (RAGGED && k >= K) {
                aReg[r] = make_float4(0.f, 0.f, 0.f, 0.f);
                bReg[r] = make_float4(0.f, 0.f, 0.f, 0.f);
            } else {
                aReg[r] = *reinterpret_cast<const float4*>(A + (m0 + row) * (long)K + k);
                bReg[r] = *reinterpret_cast<const float4*>(W + (long)(n0 + row) * K + k);
            }
        }
    };
    auto cvt1 = [&](char* base, int row, float4 v) {
        __nv_bfloat162 h01 = __floats2bfloat162_rn(v.x, v.y);
        __nv_bfloat162 h23 = __floats2bfloat162_rn(v.z, v.w);
        __nv_bfloat162 l01 = __floats2bfloat162_rn(v.x - __bfloat162float(h01.x),
                                                   v.y - __bfloat162float(h01.y));
        __nv_bfloat162 l23 = __floats2bfloat162_rn(v.z - __bfloat162float(h23.x),
                                                   v.w - __bfloat162float(h23.y));
        uint32_t* ph = reinterpret_cast<uint32_t*>(base + row * ROWB + ldCc * 8);
        uint32_t* pl = reinterpret_cast<uint32_t*>(base + row * ROWB + 64 + ldCc * 8);
        ph[0] = *reinterpret_cast<uint32_t*>(&h01);
        ph[1] = *reinterpret_cast<uint32_t*>(&h23);
        pl[0] = *reinterpret_cast<uint32_t*>(&l01);
        pl[1] = *reinterpret_cast<uint32_t*>(&l23);
    };
    auto cvt_store = [&](int s) {
        char* baseA = dsm + s * STAGEB;
        char* baseB = baseA + MATB;
#pragma unroll
        for (int r = 0; r < 4; r++) {
            cvt1(baseA, ldRow + r * 32, aReg[r]);
            cvt1(baseB, ldRow + r * 32, bReg[r]);
        }
    };

    // ldmatrix lane offsets (bytes); 144B row stride -> conflict-free mod 128
    const uint32_t aOff = (uint32_t)(lane & 15) * ROWB + (uint32_t)(lane >> 4) * 16;
    const uint32_t bOff = ((uint32_t)(((lane >> 4) & 1) * 8 + (lane & 7))) * ROWB +
                          (uint32_t)((lane >> 3) & 1) * 16;

    float acc[4][4][4];
#pragma unroll
    for (int i = 0; i < 4; i++)
#pragma unroll
        for (int j = 0; j < 4; j++)
#pragma unroll
            for (int q = 0; q < 4; q++) acc[i][j][q] = 0.f;

    auto compute = [&](int s) {
        const uint32_t uA = smem_u32(dsm + s * STAGEB);
        const uint32_t uB = uA + MATB;
#pragma unroll
        for (int kk = 0; kk < 2; kk++) {         // two 16-k sub-steps, no barrier between
            const uint32_t hiOf = (uint32_t)kk * 32;
            const uint32_t loOf = 64 + (uint32_t)kk * 32;
            uint32_t af[2][4][4], bf[2][2][4];   // [sub][tile][frag]; sub 0 = hi, 1 = lo
#pragma unroll
            for (int mt = 0; mt < 4; mt++) {
                uint32_t ro = uA + (uint32_t)(wm * 64 + mt * 16) * ROWB + aOff;
                ldmatrix_x4(af[0][mt], ro + hiOf);
                ldmatrix_x4(af[1][mt], ro + loOf);
            }
#pragma unroll
            for (int bt = 0; bt < 2; bt++) {
                uint32_t ro = uB + (uint32_t)(wn * 32 + bt * 16) * ROWB + bOff;
                ldmatrix_x4(bf[0][bt], ro + hiOf);
                ldmatrix_x4(bf[1][bt], ro + loOf);
            }
#pragma unroll
            for (int mt = 0; mt < 4; mt++)
#pragma unroll
                for (int nt = 0; nt < 4; nt++) {
                    int bt = nt >> 1, o = (nt & 1) * 2;
                    mma_bf16(acc[mt][nt], af[0][mt], bf[0][bt][o], bf[0][bt][o + 1]); // hi*hi
                    mma_bf16(acc[mt][nt], af[0][mt], bf[1][bt][o], bf[1][bt][o + 1]); // hi*lo
                    mma_bf16(acc[mt][nt], af[1][mt], bf[0][bt][o], bf[0][bt][o + 1]); // lo*hi
                }
        }
    };

    load_g(0);
    cvt_store(0);
    __syncthreads();
    for (int c = 0; c < NC; c++) {
        if (c + 1 < NC) load_g(c + 1);
        compute(c & 1);
        if (c + 1 < NC) cvt_store((c + 1) & 1);
        __syncthreads();
    }

    // epilogue (R12 layout)
#pragma unroll
    for (int mt = 0; mt < 4; mt++) {
        long mb = m0 + wm * 64 + mt * 16 + (lane >> 2);
#pragma unroll
        for (int nt = 0; nt < 4; nt++) {
            int col = wn * 32 + nt * 8 + (lane & 3) * 2;
            float b0 = sBias[col], b1 = sBias[col + 1];
#pragma unroll
            for (int h = 0; h < 2; h++) {
                float v0 = acc[mt][nt][2 * h + 0] + b0;
                float v1 = acc[mt][nt][2 * h + 1] + b1;
                float2 o;
                o.x = v0 > 0.f ? v0 : ALPHA * v0;
                o.y = v1 > 0.f ? v1 : ALPHA * v1;
                *reinterpret_cast<float2*>(Y + (mb + 8 * h) * (long)NTOT + n0 + col) = o;
            }
        }
    }
}
static constexpr int HMMA_SMEM = 2 * 2 * 128 * 144;   // 73728 B

// ================= f32x2 helpers + fp32 GEMM (kept for L5, N=32) =================
__device__ __forceinline__ unsigned long long pack2_dup(float a) {
    unsigned long long r;
    asm("mov.b64 %0, {%1, %1};" : "=l"(r) : "f"(a));
    return r;
}
__device__ __forceinline__ unsigned long long pack2(float x, float y) {
    unsigned long long r;
    asm("mov.b64 %0, {%1, %2};" : "=l"(r) : "f"(x), "f"(y));
    return r;
}
__device__ __forceinline__ void fma2(unsigned long long& d, unsigned long long a,
                                     unsigned long long b) {
    asm("fma.rn.f32x2 %0, %1, %2, %0;" : "+l"(d) : "l"(a), "l"(b));
}
__device__ __forceinline__ float2 unpack2(unsigned long long v) {
    float2 r;
    asm("mov.b64 {%0, %1}, %2;" : "=f"(r.x), "=f"(r.y) : "l"(v));
    return r;
}

template <int BM, int BN, int BK, int TM, int TN, int NT>
__global__ __launch_bounds__(NT) void gemm_lrelu_kernel(
    const float* __restrict__ A, const float* __restrict__ W,
    const float* __restrict__ bias, float* __restrict__ C, int N, int K) {
    __shared__ float As[BK][BM];
    __shared__ float Bs[BK][BN];

    const int tid = threadIdx.x;
    const long m0 = (long)blockIdx.y * BM;
    const int n0 = blockIdx.x * BN;
    constexpr int TX = BN / TN;
    const int tx = tid % TX;
    const int ty = tid / TX;
    constexpr int NACC = TN / 2;

    unsigned long long acc[TM][NACC];
#pragma unroll
    for (int i = 0; i < TM; i++)
#pragma unroll
        for (int j = 0; j < NACC; j++) acc[i][j] = 0ull;

    constexpr int KC = BK / 4;
    constexpr int AR = (BM * KC) / NT;
    constexpr int BR = (BN * KC) / NT;

    int aRow[AR], aKc[AR];
#pragma unroll
    for (int r = 0; r < AR; r++) { int i = tid + r * NT; aRow[r] = i / KC; aKc[r] = (i % KC) * 4; }
    int bRow[BR], bKc[BR];
#pragma unroll
    for (int r = 0; r < BR; r++) { int i = tid + r * NT; bRow[r] = i / KC; bKc[r] = (i % KC) * 4; }

    float4 aReg[AR], bReg[BR];
#pragma unroll
    for (int r = 0; r < AR; r++)
        aReg[r] = *reinterpret_cast<const float4*>(A + (m0 + aRow[r]) * (long)K + aKc[r]);
#pragma unroll
    for (int r = 0; r < BR; r++)
        bReg[r] = *reinterpret_cast<const float4*>(W + (long)(n0 + bRow[r]) * K + bKc[r]);

    for (int k0 = 0; k0 < K; k0 += BK) {
#pragma unroll
        for (int r = 0; r < AR; r++) {
            float4 v = aReg[r];
            As[aKc[r] + 0][aRow[r]] = v.x; As[aKc[r] + 1][aRow[r]] = v.y;
            As[aKc[r] + 2][aRow[r]] = v.z; As[aKc[r] + 3][aRow[r]] = v.w;
        }
#pragma unroll
        for (int r = 0; r < BR; r++) {
            float4 v = bReg[r];
            Bs[bKc[r] + 0][bRow[r]] = v.x; Bs[bKc[r] + 1][bRow[r]] = v.y;
            Bs[bKc[r] + 2][bRow[r]] = v.z; Bs[bKc[r] + 3][bRow[r]] = v.w;
        }
        __syncthreads();

        int kn = k0 + BK;
        if (kn < K) {
#pragma unroll
            for (int r = 0; r < AR; r++)
                aReg[r] = *reinterpret_cast<const float4*>(A + (m0 + aRow[r]) * (long)K + kn + aKc[r]);
#pragma unroll
            for (int r = 0; r < BR; r++)
                bReg[r] = *reinterpret_cast<const float4*>(W + (long)(n0 + bRow[r]) * K + kn + bKc[r]);
        }

#pragma unroll
        for (int k = 0; k < BK; k++) {
            unsigned long long a2[TM];
#pragma unroll
            for (int i = 0; i < TM; i += 4) {
                float4 av = *reinterpret_cast<const float4*>(&As[k][ty * TM + i]);
                a2[i + 0] = pack2_dup(av.x); a2[i + 1] = pack2_dup(av.y);
                a2[i + 2] = pack2_dup(av.z); a2[i + 3] = pack2_dup(av.w);
            }
            unsigned long long b2[NACC];
#pragma unroll
            for (int j = 0; j < NACC; j += 2) {
                float4 bv = *reinterpret_cast<const float4*>(&Bs[k][tx * TN + 2 * j]);
                b2[j + 0] = pack2(bv.x, bv.y); b2[j + 1] = pack2(bv.z, bv.w);
            }
#pragma unroll
            for (int i = 0; i < TM; i++)
#pragma unroll
                for (int j = 0; j < NACC; j++) fma2(acc[i][j], a2[i], b2[j]);
        }
        __syncthreads();
    }

#pragma unroll
    for (int i = 0; i < TM; i++) {
        long m = m0 + ty * TM + i;
#pragma unroll
        for (int j = 0; j < NACC; j++) {
            int n = n0 + tx * TN + 2 * j;
            float2 v = unpack2(acc[i][j]);
            float v0 = v.x + bias[n];
            float v1 = v.y + bias[n + 1];
            v0 = v0 > 0.f ? v0 : ALPHA * v0;
            v1 = v1 > 0.f ? v1 : ALPHA * v1;
            float2 o; o.x = v0; o.y = v1;
            *reinterpret_cast<float2*>(C + m * (long)N + n) = o;
        }
    }
}

// ---------------- warp-per-row histogram entropy (no block barriers) ----------------
template <int D>
__global__ __launch_bounds__(256) void hist_entropy_warp_kernel(
    const float* __restrict__ Y, const float* __restrict__ clog,
    double* __restrict__ part) {
    constexpr int E = D / 32;                 // elems per lane (4 or 8)
    __shared__ int hist[8][D];
    const int lane = threadIdx.x & 31;
    const int w = threadIdx.x >> 5;
    const long row = (long)blockIdx.x * 8 + w;

    float v[E];
#pragma unroll
    for (int i = 0; i < E; i += 4) {
        float4 t = *reinterpret_cast<const float4*>(Y + row * D + lane * E + i);
        v[i] = t.x; v[i + 1] = t.y; v[i + 2] = t.z; v[i + 3] = t.w;
    }

    float mn = v[0], mx = v[0];
#pragma unroll
    for (int i = 1; i < E; i++) { mn = fminf(mn, v[i]); mx = fmaxf(mx, v[i]); }
#pragma unroll
    for (int o = 16; o > 0; o >>= 1) {
        mn = fminf(mn, __shfl_xor_sync(0xffffffffu, mn, o));
        mx = fmaxf(mx, __shfl_xor_sync(0xffffffffu, mx, o));
    }

#pragma unroll
    for (int i = 0; i < E; i++) hist[w][lane * E + i] = 0;
    __syncwarp();

    float width = mx - mn;
    float wsafe = width > 0.f ? width : 1.0f;
#pragma unroll
    for (int i = 0; i < E; i++) {
        float t = (v[i] - mn) / wsafe * (float)D;   // reference op order
        int b = (int)floorf(t);
        b = b < 0 ? 0 : (b > D - 1 ? D - 1 : b);
        unsigned mask = __match_any_sync(0xffffffffu, b);
        if ((__ffs(mask) - 1) == lane) atomicAdd(&hist[w][b], __popc(mask));
    }
    __syncwarp();

    float s = 0.f;
#pragma unroll
    for (int i = 0; i < E; i++) s += clog[hist[w][lane * E + i]];
#pragma unroll
    for (int o = 16; o > 0; o >>= 1) s += __shfl_xor_sync(0xffffffffu, s, o);
    if (lane == 0) {
        float H = 2.0f * logf((float)D) - s / (float)D;
        atomicAdd(&part[row & 1023], (double)H);
    }
}

__global__ __launch_bounds__(256) void hist_entropy32_kernel(const float* __restrict__ Y,
                                                             const float* __restrict__ logt,
                                                             double* __restrict__ part) {
    const int lane = threadIdx.x & 31;
    const int warp = threadIdx.x >> 5;
    const long row = (long)blockIdx.x * 8 + warp;
    float v = Y[row * 32 + lane];
    float mn = v, mx = v;
#pragma unroll
    for (int o = 16; o > 0; o >>= 1) {
        mn = fminf(mn, __shfl_xor_sync(0xffffffffu, mn, o));
        mx = fmaxf(mx, __shfl_xor_sync(0xffffffffu, mx, o));
    }
    float width = mx - mn;
    float wsafe = width > 0.f ? width : 1.0f;
    float t = (v - mn) / wsafe * 32.0f;
    int b = (int)floorf(t);
    b = b < 0 ? 0 : (b > 31 ? 31 : b);
    unsigned mask = __match_any_sync(0xffffffffu, b);
    int cnt = __popc(mask);
    float s = logt[cnt];
#pragma unroll
    for (int o = 16; o > 0; o >>= 1) s += __shfl_xor_sync(0xffffffffu, s, o);
    if (lane == 0) {
        float H = 2.0f * logf(32.0f) - s * (1.0f / 32.0f);
        atomicAdd(&part[row & 1023], (double)H);
    }
}

// ---------------- final layer: relu(y5 @ W6^T + b6) -> log_softmax ----------------
__global__ __launch_bounds__(256) void final_kernel(const float* __restrict__ Y5,
                                                    const float* __restrict__ W6,
                                                    const float* __restrict__ b6,
                                                    float* __restrict__ out) {
    __shared__ float w[320];
    __shared__ float bb[16];
    int tid = threadIdx.x;
    for (int i = tid; i < 320; i += 256) w[i] = W6[i];
    if (tid < 10) bb[tid] = b6[tid];
    __syncthreads();

    long row = (long)blockIdx.x * 256 + tid;
    float y[32];
    const float4* yp = reinterpret_cast<const float4*>(Y5 + row * 32);
#pragma unroll
    for (int i = 0; i < 8; i++) {
        float4 v = yp[i];
        y[4 * i] = v.x; y[4 * i + 1] = v.y; y[4 * i + 2] = v.z; y[4 * i + 3] = v.w;
    }
    float z[10];
#pragma unroll
    for (int j = 0; j < 10; j++) {
        float s = bb[j];
#pragma unroll
        for (int k = 0; k < 32; k++) s = fmaf(y[k], w[j * 32 + k], s);
        z[j] = s > 0.f ? s : 0.f;
    }
    float m = z[0];
#pragma unroll
    for (int j = 1; j < 10; j++) m = fmaxf(m, z[j]);
    float se = 0.f;
#pragma unroll
    for (int j = 0; j < 10; j++) se += expf(z[j] - m);
    float l = logf(se);
#pragma unroll
    for (int j = 0; j < 10; j++) out[row * 10 + j] = z[j] - m - l;
}

// ---------------- init: zero partials + fill log tables ----------------
__global__ void init_kernel() {
    int i = blockIdx.x * blockDim.x + threadIdx.x;
    if (i < 5 * 1024) g_part[i] = 0.0;
    if (i < 257) {
        float fi = (float)i;
        g_clog[i] = i > 0 ? fi * logf(fi) : 0.f;
        g_logt[i] = i > 0 ? logf(fi) : 0.f;
    }
}

__global__ __launch_bounds__(256) void finish_kernel(const double* __restrict__ part,
                                                     float* __restrict__ outH) {
    __shared__ double s[256];
    int layer = blockIdx.x;
    double a = 0.0;
    for (int i = threadIdx.x; i < 1024; i += 256) a += part[layer * 1024 + i];
    s[threadIdx.x] = a;
    __syncthreads();
    for (int o = 128; o > 0; o >>= 1) {
        if (threadIdx.x < o) s[threadIdx.x] += s[threadIdx.x + o];
        __syncthreads();
    }
    if (threadIdx.x == 0) outH[layer] = (float)(s[0] / 65536.0);
}

// ---------------- launch ----------------
extern "C" void kernel_launch(void* const* d_in, const int* in_sizes, int n_in,
                              void* d_out, int out_size) {
    (void)in_sizes; (void)n_in;
    const float* x  = (const float*)d_in[0];
    const float* W1 = (const float*)d_in[1];
    const float* b1 = (const float*)d_in[2];
    const float* W2 = (const float*)d_in[3];
    const float* b2 = (const float*)d_in[4];
    const float* W3 = (const float*)d_in[5];
    const float* b3 = (const float*)d_in[6];
    const float* W4 = (const float*)d_in[7];
    const float* b4 = (const float*)d_in[8];
    const float* W5 = (const float*)d_in[9];
    const float* b5 = (const float*)d_in[10];
    const float* W6 = (const float*)d_in[11];
    const float* b6 = (const float*)d_in[12];
    float* out = (float*)d_out;
    float* outH = out + (out_size - 5);

    float *y1, *y2, *y3, *y4, *y5, *clog, *logt;
    double* part;
    cudaGetSymbolAddress((void**)&y1, g_y1);
    cudaGetSymbolAddress((void**)&y2, g_y2);
    cudaGetSymbolAddress((void**)&y3, g_y3);
    cudaGetSymbolAddress((void**)&y4, g_y4);
    cudaGetSymbolAddress((void**)&y5, g_y5);
    cudaGetSymbolAddress((void**)&part, g_part);
    cudaGetSymbolAddress((void**)&clog, g_clog);
    cudaGetSymbolAddress((void**)&logt, g_logt);

    cudaFuncSetAttribute(hmma_gemm_kernel<256, 784>,
                         cudaFuncAttributeMaxDynamicSharedMemorySize, HMMA_SMEM);
    cudaFuncSetAttribute(hmma_gemm_kernel<128, 256>,
                         cudaFuncAttributeMaxDynamicSharedMemorySize, HMMA_SMEM);
    cudaFuncSetAttribute(hmma_gemm_kernel<128, 128>,
                         cudaFuncAttributeMaxDynamicSharedMemorySize, HMMA_SMEM);

    init_kernel<<<20, 256>>>();

    // L1: [65536,784] x [256,784]^T -> y1
    hmma_gemm_kernel<256, 784><<<dim3(2, BATCH / 128), 256, HMMA_SMEM>>>(x, W1, b1, y1);
    hist_entropy_warp_kernel<256><<<BATCH / 8, 256>>>(y1, clog, part + 0 * 1024);

    // L2
    hmma_gemm_kernel<128, 256><<<dim3(1, BATCH / 128), 256, HMMA_SMEM>>>(y1, W2, b2, y2);
    hist_entropy_warp_kernel<128><<<BATCH / 8, 256>>>(y2, clog, part + 1 * 1024);

    // L3
    hmma_gemm_kernel<128, 128><<<dim3(1, BATCH / 128), 256, HMMA_SMEM>>>(y2, W3, b3, y3);
    hist_entropy_warp_kernel<128><<<BATCH / 8, 256>>>(y3, clog, part + 2 * 1024);

    // L4
    hmma_gemm_kernel<128, 128><<<dim3(1, BATCH / 128), 256, HMMA_SMEM>>>(y3, W4, b4, y4);
    hist_entropy_warp_kernel<128><<<BATCH / 8, 256>>>(y4, clog, part + 3 * 1024);

    // L5: N=32 — proven f32x2 kernel (1.5% of FLOPs)
    gemm_lrelu_kernel<128, 32, 16, 8, 4, 128>
        <<<dim3(1, BATCH / 128), 128>>>(y4, W5, b5, y5, 32, 128);
    hist_entropy32_kernel<<<BATCH / 8, 256>>>(y5, logt, part + 4 * 1024);

    // L6 + log_softmax
    final_kernel<<<BATCH / 256, 256>>>(y5, W6, b6, out);

    finish_kernel<<<5, 256>>>(part, outH);
}

// round 16
// speedup vs baseline: 1.0481x; 1.0481x over previous
#include <cuda_runtime.h>
#include <cuda_bf16.h>
#include <math.h>
#include <stdint.h>

#define ALPHA 0.01f
#define BATCH 65536

// ---------------- device scratch (no runtime allocation allowed) ----------------
__device__ float g_y1[65536 * 256];
__device__ float g_y2[65536 * 128];
__device__ float g_y3[65536 * 128];
__device__ float g_y4[65536 * 128];
__device__ float g_y5[65536 * 32];
__device__ double g_part[5 * 1024];
__device__ float g_clog[257];   // c * log(c)
__device__ float g_logt[257];   // log(c)

// ---------------- helpers ----------------
__device__ __forceinline__ uint32_t smem_u32(const void* p) {
    uint32_t a;
    asm("{ .reg .u64 t; cvta.to.shared.u64 t, %1; cvt.u32.u64 %0, t; }" : "=r"(a) : "l"(p));
    return a;
}
__device__ __forceinline__ void ldmatrix_x4(uint32_t* r, uint32_t addr) {
    asm volatile("ldmatrix.sync.aligned.m8n8.x4.shared.b16 {%0,%1,%2,%3}, [%4];"
                 : "=r"(r[0]), "=r"(r[1]), "=r"(r[2]), "=r"(r[3]) : "r"(addr));
}
__device__ __forceinline__ void mma_bf16(float* c, const uint32_t* a, uint32_t b0, uint32_t b1) {
    asm volatile(
        "mma.sync.aligned.m16n8k16.row.col.f32.bf16.bf16.f32 "
        "{%0,%1,%2,%3}, {%4,%5,%6,%7}, {%8,%9}, {%0,%1,%2,%3};"
        : "+f"(c[0]), "+f"(c[1]), "+f"(c[2]), "+f"(c[3])
        : "r"(a[0]), "r"(a[1]), "r"(a[2]), "r"(a[3]), "r"(b0), "r"(b1));
}

// ============ HMMA GEMM core (exact R12 541us config: 8 warps of 64x32, BK=16) ============
// bf16 hi/lo side-by-side (cols 0-15 hi, 16-31 lo); 3 MMAs per 16-k: ah*bh + ah*bl + al*bh.
// If FUSE_HIST: NTOT must be 128 with grid.x==1 (CTA owns complete rows); after the
// epilogue each warp re-reads 16 own rows (L2-hot) and accumulates histogram entropy.
template <int NTOT, int K, bool FUSE_HIST>
__global__ __launch_bounds__(256) void hmma_gemm_kernel(
    const float* __restrict__ A, const float* __restrict__ W,
    const float* __restrict__ bias, float* __restrict__ Y,
    const float* __restrict__ clog, double* __restrict__ part) {
    constexpr int NC = K / 16;
    constexpr int PAD = 40;                  // 32 bf16 data cols (hi|lo) + 8 pad; 80B rows
    __shared__ __align__(16) __nv_bfloat16 sA[2][128][PAD];
    __shared__ __align__(16) __nv_bfloat16 sB[2][128][PAD];
    __shared__ float sBias[128];
    __shared__ int sHist[FUSE_HIST ? 8 : 1][FUSE_HIST ? 128 : 1];

    const int tid = threadIdx.x;
    const int lane = tid & 31;
    const int w = tid >> 5;
    const int wm = w & 1;                    // 2 warps along M (64 each)
    const int wn = w >> 1;                   // 4 warps along N (32 each)
    const long m0 = (long)blockIdx.y * 128;
    const int n0 = blockIdx.x * 128;

    if (tid < 128) sBias[tid] = bias[n0 + tid];

    const int ldRow = tid >> 2;              // 0..63 (+64)
    const int ldCc = tid & 3;                // float4 index within 16 floats

    float4 aReg[2], bReg[2];
    auto load_g = [&](int c) {
        int k = c * 16 + ldCc * 4;
#pragma unroll
        for (int r = 0; r < 2; r++) {
            int row = ldRow + r * 64;
            aReg[r] = *reinterpret_cast<const float4*>(A + (m0 + row) * (long)K + k);
            bReg[r] = *reinterpret_cast<const float4*>(W + (long)(n0 + row) * K + k);
        }
    };
    auto cvt1 = [&](__nv_bfloat16 (*S)[PAD], int row, float4 v) {
        __nv_bfloat162 h01 = __floats2bfloat162_rn(v.x, v.y);
        __nv_bfloat162 h23 = __floats2bfloat162_rn(v.z, v.w);
        __nv_bfloat162 l01 = __floats2bfloat162_rn(v.x - __bfloat162float(h01.x),
                                                   v.y - __bfloat162float(h01.y));
        __nv_bfloat162 l23 = __floats2bfloat162_rn(v.z - __bfloat162float(h23.x),
                                                   v.w - __bfloat162float(h23.y));
        uint32_t* ph = reinterpret_cast<uint32_t*>(&S[row][ldCc * 4]);       // hi cols 0-15
        uint32_t* pl = reinterpret_cast<uint32_t*>(&S[row][16 + ldCc * 4]);  // lo cols 16-31
        ph[0] = *reinterpret_cast<uint32_t*>(&h01);
        ph[1] = *reinterpret_cast<uint32_t*>(&h23);
        pl[0] = *reinterpret_cast<uint32_t*>(&l01);
        pl[1] = *reinterpret_cast<uint32_t*>(&l23);
    };
    auto cvt_store = [&](int s) {
#pragma unroll
        for (int r = 0; r < 2; r++) {
            cvt1(sA[s], ldRow + r * 64, aReg[r]);
            cvt1(sB[s], ldRow + r * 64, bReg[r]);
        }
    };

    const uint32_t aOff = (uint32_t)(lane & 15) * 80 + (uint32_t)(lane >> 4) * 16;
    const uint32_t bOff = ((uint32_t)(((lane >> 4) & 1) * 8 + (lane & 7))) * 80 +
                          (uint32_t)((lane >> 3) & 1) * 16;

    float acc[4][4][4];
#pragma unroll
    for (int i = 0; i < 4; i++)
#pragma unroll
        for (int j = 0; j < 4; j++)
#pragma unroll
            for (int q = 0; q < 4; q++) acc[i][j][q] = 0.f;

    auto compute = [&](int s) {
        const uint32_t uA = smem_u32(&sA[s][0][0]);
        const uint32_t uB = smem_u32(&sB[s][0][0]);
        uint32_t af[2][4][4], bf[2][2][4];   // [sub][tile][frag]; sub 0 = hi, 1 = lo
#pragma unroll
        for (int sub = 0; sub < 2; sub++) {
#pragma unroll
            for (int mt = 0; mt < 4; mt++)
                ldmatrix_x4(af[sub][mt],
                            uA + (uint32_t)(wm * 64 + mt * 16) * 80 + sub * 32 + aOff);
#pragma unroll
            for (int bt = 0; bt < 2; bt++)
                ldmatrix_x4(bf[sub][bt],
                            uB + (uint32_t)(wn * 32 + bt * 16) * 80 + sub * 32 + bOff);
        }
#pragma unroll
        for (int mt = 0; mt < 4; mt++)
#pragma unroll
            for (int nt = 0; nt < 4; nt++) {
                int bt = nt >> 1, o = (nt & 1) * 2;
                mma_bf16(acc[mt][nt], af[0][mt], bf[0][bt][o], bf[0][bt][o + 1]); // hi*hi
                mma_bf16(acc[mt][nt], af[0][mt], bf[1][bt][o], bf[1][bt][o + 1]); // hi*lo
                mma_bf16(acc[mt][nt], af[1][mt], bf[0][bt][o], bf[0][bt][o + 1]); // lo*hi
            }
    };

    load_g(0);
    cvt_store(0);
    __syncthreads();
    for (int c = 0; c < NC; c++) {
        if (c + 1 < NC) load_g(c + 1);
        compute(c & 1);
        if (c + 1 < NC) cvt_store((c + 1) & 1);
        __syncthreads();
    }

    // epilogue
#pragma unroll
    for (int mt = 0; mt < 4; mt++) {
        long mb = m0 + wm * 64 + mt * 16 + (lane >> 2);
#pragma unroll
        for (int nt = 0; nt < 4; nt++) {
            int col = wn * 32 + nt * 8 + (lane & 3) * 2;
            float b0 = sBias[col], b1 = sBias[col + 1];
#pragma unroll
            for (int h = 0; h < 2; h++) {
                float v0 = acc[mt][nt][2 * h + 0] + b0;
                float v1 = acc[mt][nt][2 * h + 1] + b1;
                float2 o;
                o.x = v0 > 0.f ? v0 : ALPHA * v0;
                o.y = v1 > 0.f ? v1 : ALPHA * v1;
                *reinterpret_cast<float2*>(Y + (mb + 8 * h) * (long)NTOT + n0 + col) = o;
            }
        }
    }

    if (FUSE_HIST) {
        // __syncthreads orders the CTA's global stores before the re-reads below
        __syncthreads();
        for (int rr = 0; rr < 16; rr++) {
            int lrow = w * 16 + rr;
            long row = m0 + lrow;
            float4 t = *reinterpret_cast<const float4*>(Y + row * 128 + lane * 4);
            float v[4] = {t.x, t.y, t.z, t.w};

            float mn = fminf(fminf(v[0], v[1]), fminf(v[2], v[3]));
            float mx = fmaxf(fmaxf(v[0], v[1]), fmaxf(v[2], v[3]));
#pragma unroll
            for (int o = 16; o > 0; o >>= 1) {
                mn = fminf(mn, __shfl_xor_sync(0xffffffffu, mn, o));
                mx = fmaxf(mx, __shfl_xor_sync(0xffffffffu, mx, o));
            }

#pragma unroll
            for (int i = 0; i < 4; i++) sHist[w][lane * 4 + i] = 0;
            __syncwarp();

            float width = mx - mn;
            float wsafe = width > 0.f ? width : 1.0f;
#pragma unroll
            for (int i = 0; i < 4; i++) {
                float tt = (v[i] - mn) / wsafe * 128.0f;   // reference op order
                int b = (int)floorf(tt);
                b = b < 0 ? 0 : (b > 127 ? 127 : b);
                unsigned mask = __match_any_sync(0xffffffffu, b);
                if ((__ffs(mask) - 1) == lane) atomicAdd(&sHist[w][b], __popc(mask));
            }
            __syncwarp();

            float s = 0.f;
#pragma unroll
            for (int i = 0; i < 4; i++) s += clog[sHist[w][lane * 4 + i]];
#pragma unroll
            for (int o = 16; o > 0; o >>= 1) s += __shfl_xor_sync(0xffffffffu, s, o);
            if (lane == 0) {
                float H = 2.0f * logf(128.0f) - s * (1.0f / 128.0f);
                atomicAdd(&part[row & 1023], (double)H);
            }
        }
    }
}

// ================= f32x2 helpers + fp32 GEMM (kept for L5, N=32) =================
__device__ __forceinline__ unsigned long long pack2_dup(float a) {
    unsigned long long r;
    asm("mov.b64 %0, {%1, %1};" : "=l"(r) : "f"(a));
    return r;
}
__device__ __forceinline__ unsigned long long pack2(float x, float y) {
    unsigned long long r;
    asm("mov.b64 %0, {%1, %2};" : "=l"(r) : "f"(x), "f"(y));
    return r;
}
__device__ __forceinline__ void fma2(unsigned long long& d, unsigned long long a,
                                     unsigned long long b) {
    asm("fma.rn.f32x2 %0, %1, %2, %0;" : "+l"(d) : "l"(a), "l"(b));
}
__device__ __forceinline__ float2 unpack2(unsigned long long v) {
    float2 r;
    asm("mov.b64 {%0, %1}, %2;" : "=f"(r.x), "=f"(r.y) : "l"(v));
    return r;
}

template <int BM, int BN, int BK, int TM, int TN, int NT>
__global__ __launch_bounds__(NT) void gemm_lrelu_kernel(
    const float* __restrict__ A, const float* __restrict__ W,
    const float* __restrict__ bias, float* __restrict__ C, int N, int K) {
    __shared__ float As[BK][BM];
    __shared__ float Bs[BK][BN];

    const int tid = threadIdx.x;
    const long m0 = (long)blockIdx.y * BM;
    const int n0 = blockIdx.x * BN;
    constexpr int TX = BN / TN;
    const int tx = tid % TX;
    const int ty = tid / TX;
    constexpr int NACC = TN / 2;

    unsigned long long acc[TM][NACC];
#pragma unroll
    for (int i = 0; i < TM; i++)
#pragma unroll
        for (int j = 0; j < NACC; j++) acc[i][j] = 0ull;

    constexpr int KC = BK / 4;
    constexpr int AR = (BM * KC) / NT;
    constexpr int BR = (BN * KC) / NT;

    int aRow[AR], aKc[AR];
#pragma unroll
    for (int r = 0; r < AR; r++) { int i = tid + r * NT; aRow[r] = i / KC; aKc[r] = (i % KC) * 4; }
    int bRow[BR], bKc[BR];
#pragma unroll
    for (int r = 0; r < BR; r++) { int i = tid + r * NT; bRow[r] = i / KC; bKc[r] = (i % KC) * 4; }

    float4 aReg[AR], bReg[BR];
#pragma unroll
    for (int r = 0; r < AR; r++)
        aReg[r] = *reinterpret_cast<const float4*>(A + (m0 + aRow[r]) * (long)K + aKc[r]);
#pragma unroll
    for (int r = 0; r < BR; r++)
        bReg[r] = *reinterpret_cast<const float4*>(W + (long)(n0 + bRow[r]) * K + bKc[r]);

    for (int k0 = 0; k0 < K; k0 += BK) {
#pragma unroll
        for (int r = 0; r < AR; r++) {
            float4 v = aReg[r];
            As[aKc[r] + 0][aRow[r]] = v.x; As[aKc[r] + 1][aRow[r]] = v.y;
            As[aKc[r] + 2][aRow[r]] = v.z; As[aKc[r] + 3][aRow[r]] = v.w;
        }
#pragma unroll
        for (int r = 0; r < BR; r++) {
            float4 v = bReg[r];
            Bs[bKc[r] + 0][bRow[r]] = v.x; Bs[bKc[r] + 1][bRow[r]] = v.y;
            Bs[bKc[r] + 2][bRow[r]] = v.z; Bs[bKc[r] + 3][bRow[r]] = v.w;
        }
        __syncthreads();

        int kn = k0 + BK;
        if (kn < K) {
#pragma unroll
            for (int r = 0; r < AR; r++)
                aReg[r] = *reinterpret_cast<const float4*>(A + (m0 + aRow[r]) * (long)K + kn + aKc[r]);
#pragma unroll
            for (int r = 0; r < BR; r++)
                bReg[r] = *reinterpret_cast<const float4*>(W + (long)(n0 + bRow[r]) * K + kn + bKc[r]);
        }

#pragma unroll
        for (int k = 0; k < BK; k++) {
            unsigned long long a2[TM];
#pragma unroll
            for (int i = 0; i < TM; i += 4) {
                float4 av = *reinterpret_cast<const float4*>(&As[k][ty * TM + i]);
                a2[i + 0] = pack2_dup(av.x); a2[i + 1] = pack2_dup(av.y);
                a2[i + 2] = pack2_dup(av.z); a2[i + 3] = pack2_dup(av.w);
            }
            unsigned long long b2[NACC];
#pragma unroll
            for (int j = 0; j < NACC; j += 2) {
                float4 bv = *reinterpret_cast<const float4*>(&Bs[k][tx * TN + 2 * j]);
                b2[j + 0] = pack2(bv.x, bv.y); b2[j + 1] = pack2(bv.z, bv.w);
            }
#pragma unroll
            for (int i = 0; i < TM; i++)
#pragma unroll
                for (int j = 0; j < NACC; j++) fma2(acc[i][j], a2[i], b2[j]);
        }
        __syncthreads();
    }

#pragma unroll
    for (int i = 0; i < TM; i++) {
        long m = m0 + ty * TM + i;
#pragma unroll
        for (int j = 0; j < NACC; j++) {
            int n = n0 + tx * TN + 2 * j;
            float2 v = unpack2(acc[i][j]);
            float v0 = v.x + bias[n];
            float v1 = v.y + bias[n + 1];
            v0 = v0 > 0.f ? v0 : ALPHA * v0;
            v1 = v1 > 0.f ? v1 : ALPHA * v1;
            float2 o; o.x = v0; o.y = v1;
            *reinterpret_cast<float2*>(C + m * (long)N + n) = o;
        }
    }
}

// ---------------- warp-per-row histogram entropy (standalone, used for L1) ----------------
template <int D>
__global__ __launch_bounds__(256) void hist_entropy_warp_kernel(
    const float* __restrict__ Y, const float* __restrict__ clog,
    double* __restrict__ part) {
    constexpr int E = D / 32;                 // elems per lane (4 or 8)
    __shared__ int hist[8][D];
    const int lane = threadIdx.x & 31;
    const int w = threadIdx.x >> 5;
    const long row = (long)blockIdx.x * 8 + w;

    float v[E];
#pragma unroll
    for (int i = 0; i < E; i += 4) {
        float4 t = *reinterpret_cast<const float4*>(Y + row * D + lane * E + i);
        v[i] = t.x; v[i + 1] = t.y; v[i + 2] = t.z; v[i + 3] = t.w;
    }

    float mn = v[0], mx = v[0];
#pragma unroll
    for (int i = 1; i < E; i++) { mn = fminf(mn, v[i]); mx = fmaxf(mx, v[i]); }
#pragma unroll
    for (int o = 16; o > 0; o >>= 1) {
        mn = fminf(mn, __shfl_xor_sync(0xffffffffu, mn, o));
        mx = fmaxf(mx, __shfl_xor_sync(0xffffffffu, mx, o));
    }

#pragma unroll
    for (int i = 0; i < E; i++) hist[w][lane * E + i] = 0;
    __syncwarp();

    float width = mx - mn;
    float wsafe = width > 0.f ? width : 1.0f;
#pragma unroll
    for (int i = 0; i < E; i++) {
        float t = (v[i] - mn) / wsafe * (float)D;   // reference op order
        int b = (int)floorf(t);
        b = b < 0 ? 0 : (b > D - 1 ? D - 1 : b);
        unsigned mask = __match_any_sync(0xffffffffu, b);
        if ((__ffs(mask) - 1) == lane) atomicAdd(&hist[w][b], __popc(mask));
    }
    __syncwarp();

    float s = 0.f;
#pragma unroll
    for (int i = 0; i < E; i++) s += clog[hist[w][lane * E + i]];
#pragma unroll
    for (int o = 16; o > 0; o >>= 1) s += __shfl_xor_sync(0xffffffffu, s, o);
    if (lane == 0) {
        float H = 2.0f * logf((float)D) - s / (float)D;
        atomicAdd(&part[row & 1023], (double)H);
    }
}

__global__ __launch_bounds__(256) void hist_entropy32_kernel(const float* __restrict__ Y,
                                                             const float* __restrict__ logt,
                                                             double* __restrict__ part) {
    const int lane = threadIdx.x & 31;
    const int warp = threadIdx.x >> 5;
    const long row = (long)blockIdx.x * 8 + warp;
    float v = Y[row * 32 + lane];
    float mn = v, mx = v;
#pragma unroll
    for (int o = 16; o > 0; o >>= 1) {
        mn = fminf(mn, __shfl_xor_sync(0xffffffffu, mn, o));
        mx = fmaxf(mx, __shfl_xor_sync(0xffffffffu, mx, o));
    }
    float width = mx - mn;
    float wsafe = width > 0.f ? width : 1.0f;
    float t = (v - mn) / wsafe * 32.0f;
    int b = (int)floorf(t);
    b = b < 0 ? 0 : (b > 31 ? 31 : b);
    unsigned mask = __match_any_sync(0xffffffffu, b);
    int cnt = __popc(mask);
    float s = logt[cnt];
#pragma unroll
    for (int o = 16; o > 0; o >>= 1) s += __shfl_xor_sync(0xffffffffu, s, o);
    if (lane == 0) {
        float H = 2.0f * logf(32.0f) - s * (1.0f / 32.0f);
        atomicAdd(&part[row & 1023], (double)H);
    }
}

// ---------------- final layer: relu(y5 @ W6^T + b6) -> log_softmax ----------------
__global__ __launch_bounds__(256) void final_kernel(const float* __restrict__ Y5,
                                                    const float* __restrict__ W6,
                                                    const float* __restrict__ b6,
                                                    float* __restrict__ out) {
    __shared__ float w[320];
    __shared__ float bb[16];
    int tid = threadIdx.x;
    for (int i = tid; i < 320; i += 256) w[i] = W6[i];
    if (tid < 10) bb[tid] = b6[tid];
    __syncthreads();

    long row = (long)blockIdx.x * 256 + tid;
    float y[32];
    const float4* yp = reinterpret_cast<const float4*>(Y5 + row * 32);
#pragma unroll
    for (int i = 0; i < 8; i++) {
        float4 v = yp[i];
        y[4 * i] = v.x; y[4 * i + 1] = v.y; y[4 * i + 2] = v.z; y[4 * i + 3] = v.w;
    }
    float z[10];
#pragma unroll
    for (int j = 0; j < 10; j++) {
        float s = bb[j];
#pragma unroll
        for (int k = 0; k < 32; k++) s = fmaf(y[k], w[j * 32 + k], s);
        z[j] = s > 0.f ? s : 0.f;
    }
    float m = z[0];
#pragma unroll
    for (int j = 1; j < 10; j++) m = fmaxf(m, z[j]);
    float se = 0.f;
#pragma unroll
    for (int j = 0; j < 10; j++) se += expf(z[j] - m);
    float l = logf(se);
#pragma unroll
    for (int j = 0; j < 10; j++) out[row * 10 + j] = z[j] - m - l;
}

// ---------------- init: zero partials + fill log tables ----------------
__global__ void init_kernel() {
    int i = blockIdx.x * blockDim.x + threadIdx.x;
    if (i < 5 * 1024) g_part[i] = 0.0;
    if (i < 257) {
        float fi = (float)i;
        g_clog[i] = i > 0 ? fi * logf(fi) : 0.f;
        g_logt[i] = i > 0 ? logf(fi) : 0.f;
    }
}

__global__ __launch_bounds__(256) void finish_kernel(const double* __restrict__ part,
                                                     float* __restrict__ outH) {
    __shared__ double s[256];
    int layer = blockIdx.x;
    double a = 0.0;
    for (int i = threadIdx.x; i < 1024; i += 256) a += part[layer * 1024 + i];
    s[threadIdx.x] = a;
    __syncthreads();
    for (int o = 128; o > 0; o >>= 1) {
        if (threadIdx.x < o) s[threadIdx.x] += s[threadIdx.x + o];
        __syncthreads();
    }
    if (threadIdx.x == 0) outH[layer] = (float)(s[0] / 65536.0);
}

// ---------------- launch ----------------
extern "C" void kernel_launch(void* const* d_in, const int* in_sizes, int n_in,
                              void* d_out, int out_size) {
    (void)in_sizes; (void)n_in;
    const float* x  = (const float*)d_in[0];
    const float* W1 = (const float*)d_in[1];
    const float* b1 = (const float*)d_in[2];
    const float* W2 = (const float*)d_in[3];
    const float* b2 = (const float*)d_in[4];
    const float* W3 = (const float*)d_in[5];
    const float* b3 = (const float*)d_in[6];
    const float* W4 = (const float*)d_in[7];
    const float* b4 = (const float*)d_in[8];
    const float* W5 = (const float*)d_in[9];
    const float* b5 = (const float*)d_in[10];
    const float* W6 = (const float*)d_in[11];
    const float* b6 = (const float*)d_in[12];
    float* out = (float*)d_out;
    float* outH = out + (out_size - 5);

    float *y1, *y2, *y3, *y4, *y5, *clog, *logt;
    double* part;
    cudaGetSymbolAddress((void**)&y1, g_y1);
    cudaGetSymbolAddress((void**)&y2, g_y2);
    cudaGetSymbolAddress((void**)&y3, g_y3);
    cudaGetSymbolAddress((void**)&y4, g_y4);
    cudaGetSymbolAddress((void**)&y5, g_y5);
    cudaGetSymbolAddress((void**)&part, g_part);
    cudaGetSymbolAddress((void**)&clog, g_clog);
    cudaGetSymbolAddress((void**)&logt, g_logt);

    init_kernel<<<20, 256>>>();

    // L1: [65536,784] x [256,784]^T -> y1 (grid.x=2, rows split -> standalone hist)
    hmma_gemm_kernel<256, 784, false>
        <<<dim3(2, BATCH / 128), 256>>>(x, W1, b1, y1, clog, part);
    hist_entropy_warp_kernel<256><<<BATCH / 8, 256>>>(y1, clog, part + 0 * 1024);

    // L2 (fused hist: CTA owns complete 128-wide rows)
    hmma_gemm_kernel<128, 256, true>
        <<<dim3(1, BATCH / 128), 256>>>(y1, W2, b2, y2, clog, part + 1 * 1024);

    // L3
    hmma_gemm_kernel<128, 128, true>
        <<<dim3(1, BATCH / 128), 256>>>(y2, W3, b3, y3, clog, part + 2 * 1024);

    // L4
    hmma_gemm_kernel<128, 128, true>
        <<<dim3(1, BATCH / 128), 256>>>(y3, W4, b4, y4, clog, part + 3 * 1024);

    // L5: N=32 — proven f32x2 kernel (1.5% of FLOPs)
    gemm_lrelu_kernel<128, 32, 16, 8, 4, 128>
        <<<dim3(1, BATCH / 128), 128>>>(y4, W5, b5, y5, 32, 128);
    hist_entropy32_kernel<<<BATCH / 8, 256>>>(y5, logt, part + 4 * 1024);

    // L6 + log_softmax
    final_kernel<<<BATCH / 256, 256>>>(y5, W6, b6, out);

    finish_kernel<<<5, 256>>>(part, outH);
}

// round 17
// speedup vs baseline: 1.1305x; 1.0786x over previous
#include <cuda_runtime.h>
#include <cuda_bf16.h>
#include <math.h>
#include <stdint.h>

#define ALPHA 0.01f
#define BATCH 65536

// ---------------- device scratch (no runtime allocation allowed) ----------------
__device__ float g_y1[65536 * 256];
__device__ float g_y2[65536 * 128];
__device__ float g_y3[65536 * 128];
__device__ float g_y4[65536 * 128];
__device__ float g_y5[65536 * 32];
__device__ double g_part[5 * 1024];
__device__ float g_clog[257];   // c * log(c)
__device__ float g_logt[257];   // log(c)

// ---------------- helpers ----------------
__device__ __forceinline__ uint32_t smem_u32(const void* p) {
    uint32_t a;
    asm("{ .reg .u64 t; cvta.to.shared.u64 t, %1; cvt.u32.u64 %0, t; }" : "=r"(a) : "l"(p));
    return a;
}
__device__ __forceinline__ void ldmatrix_x4(uint32_t* r, uint32_t addr) {
    asm volatile("ldmatrix.sync.aligned.m8n8.x4.shared.b16 {%0,%1,%2,%3}, [%4];"
                 : "=r"(r[0]), "=r"(r[1]), "=r"(r[2]), "=r"(r[3]) : "r"(addr));
}
__device__ __forceinline__ void mma_bf16(float* c, const uint32_t* a, uint32_t b0, uint32_t b1) {
    asm volatile(
        "mma.sync.aligned.m16n8k16.row.col.f32.bf16.bf16.f32 "
        "{%0,%1,%2,%3}, {%4,%5,%6,%7}, {%8,%9}, {%0,%1,%2,%3};"
        : "+f"(c[0]), "+f"(c[1]), "+f"(c[2]), "+f"(c[3])
        : "r"(a[0]), "r"(a[1]), "r"(a[2]), "r"(a[3]), "r"(b0), "r"(b1));
}

// ============ HMMA GEMM (exact R12 541us config: 8 warps of 64x32, BK=16) ============
// bf16 hi/lo side-by-side (cols 0-15 hi, 16-31 lo); 3 MMAs per 16-k: ah*bh + ah*bl + al*bh.
template <int NTOT, int K>
__global__ __launch_bounds__(256) void hmma_gemm_kernel(
    const float* __restrict__ A, const float* __restrict__ W,
    const float* __restrict__ bias, float* __restrict__ Y) {
    constexpr int NC = K / 16;
    constexpr int PAD = 40;                  // 32 bf16 data cols (hi|lo) + 8 pad; 80B rows
    __shared__ __align__(16) __nv_bfloat16 sA[2][128][PAD];
    __shared__ __align__(16) __nv_bfloat16 sB[2][128][PAD];
    __shared__ float sBias[128];

    const int tid = threadIdx.x;
    const int lane = tid & 31;
    const int w = tid >> 5;
    const int wm = w & 1;                    // 2 warps along M (64 each)
    const int wn = w >> 1;                   // 4 warps along N (32 each)
    const long m0 = (long)blockIdx.y * 128;
    const int n0 = blockIdx.x * 128;

    if (tid < 128) sBias[tid] = bias[n0 + tid];

    const int ldRow = tid >> 2;              // 0..63 (+64)
    const int ldCc = tid & 3;                // float4 index within 16 floats

    float4 aReg[2], bReg[2];
    auto load_g = [&](int c) {
        int k = c * 16 + ldCc * 4;
#pragma unroll
        for (int r = 0; r < 2; r++) {
            int row = ldRow + r * 64;
            aReg[r] = *reinterpret_cast<const float4*>(A + (m0 + row) * (long)K + k);
            bReg[r] = *reinterpret_cast<const float4*>(W + (long)(n0 + row) * K + k);
        }
    };
    auto cvt1 = [&](__nv_bfloat16 (*S)[PAD], int row, float4 v) {
        __nv_bfloat162 h01 = __floats2bfloat162_rn(v.x, v.y);
        __nv_bfloat162 h23 = __floats2bfloat162_rn(v.z, v.w);
        __nv_bfloat162 l01 = __floats2bfloat162_rn(v.x - __bfloat162float(h01.x),
                                                   v.y - __bfloat162float(h01.y));
        __nv_bfloat162 l23 = __floats2bfloat162_rn(v.z - __bfloat162float(h23.x),
                                                   v.w - __bfloat162float(h23.y));
        uint32_t* ph = reinterpret_cast<uint32_t*>(&S[row][ldCc * 4]);       // hi cols 0-15
        uint32_t* pl = reinterpret_cast<uint32_t*>(&S[row][16 + ldCc * 4]);  // lo cols 16-31
        ph[0] = *reinterpret_cast<uint32_t*>(&h01);
        ph[1] = *reinterpret_cast<uint32_t*>(&h23);
        pl[0] = *reinterpret_cast<uint32_t*>(&l01);
        pl[1] = *reinterpret_cast<uint32_t*>(&l23);
    };
    auto cvt_store = [&](int s) {
#pragma unroll
        for (int r = 0; r < 2; r++) {
            cvt1(sA[s], ldRow + r * 64, aReg[r]);
            cvt1(sB[s], ldRow + r * 64, bReg[r]);
        }
    };

    const uint32_t aOff = (uint32_t)(lane & 15) * 80 + (uint32_t)(lane >> 4) * 16;
    const uint32_t bOff = ((uint32_t)(((lane >> 4) & 1) * 8 + (lane & 7))) * 80 +
                          (uint32_t)((lane >> 3) & 1) * 16;

    float acc[4][4][4];
#pragma unroll
    for (int i = 0; i < 4; i++)
#pragma unroll
        for (int j = 0; j < 4; j++)
#pragma unroll
            for (int q = 0; q < 4; q++) acc[i][j][q] = 0.f;

    auto compute = [&](int s) {
        const uint32_t uA = smem_u32(&sA[s][0][0]);
        const uint32_t uB = smem_u32(&sB[s][0][0]);
        uint32_t af[2][4][4], bf[2][2][4];   // [sub][tile][frag]; sub 0 = hi, 1 = lo
#pragma unroll
        for (int sub = 0; sub < 2; sub++) {
#pragma unroll
            for (int mt = 0; mt < 4; mt++)
                ldmatrix_x4(af[sub][mt],
                            uA + (uint32_t)(wm * 64 + mt * 16) * 80 + sub * 32 + aOff);
#pragma unroll
            for (int bt = 0; bt < 2; bt++)
                ldmatrix_x4(bf[sub][bt],
                            uB + (uint32_t)(wn * 32 + bt * 16) * 80 + sub * 32 + bOff);
        }
#pragma unroll
        for (int mt = 0; mt < 4; mt++)
#pragma unroll
            for (int nt = 0; nt < 4; nt++) {
                int bt = nt >> 1, o = (nt & 1) * 2;
                mma_bf16(acc[mt][nt], af[0][mt], bf[0][bt][o], bf[0][bt][o + 1]); // hi*hi
                mma_bf16(acc[mt][nt], af[0][mt], bf[1][bt][o], bf[1][bt][o + 1]); // hi*lo
                mma_bf16(acc[mt][nt], af[1][mt], bf[0][bt][o], bf[0][bt][o + 1]); // lo*hi
            }
    };

    load_g(0);
    cvt_store(0);
    __syncthreads();
    for (int c = 0; c < NC; c++) {
        if (c + 1 < NC) load_g(c + 1);
        compute(c & 1);
        if (c + 1 < NC) cvt_store((c + 1) & 1);
        __syncthreads();
    }

    // epilogue
#pragma unroll
    for (int mt = 0; mt < 4; mt++) {
        long mb = m0 + wm * 64 + mt * 16 + (lane >> 2);
#pragma unroll
        for (int nt = 0; nt < 4; nt++) {
            int col = wn * 32 + nt * 8 + (lane & 3) * 2;
            float b0 = sBias[col], b1 = sBias[col + 1];
#pragma unroll
            for (int h = 0; h < 2; h++) {
                float v0 = acc[mt][nt][2 * h + 0] + b0;
                float v1 = acc[mt][nt][2 * h + 1] + b1;
                float2 o;
                o.x = v0 > 0.f ? v0 : ALPHA * v0;
                o.y = v1 > 0.f ? v1 : ALPHA * v1;
                *reinterpret_cast<float2*>(Y + (mb + 8 * h) * (long)NTOT + n0 + col) = o;
            }
        }
    }
}

// ================= f32x2 helpers + fp32 GEMM (kept for L5, N=32) =================
__device__ __forceinline__ unsigned long long pack2_dup(float a) {
    unsigned long long r;
    asm("mov.b64 %0, {%1, %1};" : "=l"(r) : "f"(a));
    return r;
}
__device__ __forceinline__ unsigned long long pack2(float x, float y) {
    unsigned long long r;
    asm("mov.b64 %0, {%1, %2};" : "=l"(r) : "f"(x), "f"(y));
    return r;
}
__device__ __forceinline__ void fma2(unsigned long long& d, unsigned long long a,
                                     unsigned long long b) {
    asm("fma.rn.f32x2 %0, %1, %2, %0;" : "+l"(d) : "l"(a), "l"(b));
}
__device__ __forceinline__ float2 unpack2(unsigned long long v) {
    float2 r;
    asm("mov.b64 {%0, %1}, %2;" : "=f"(r.x), "=f"(r.y) : "l"(v));
    return r;
}

template <int BM, int BN, int BK, int TM, int TN, int NT>
__global__ __launch_bounds__(NT) void gemm_lrelu_kernel(
    const float* __restrict__ A, const float* __restrict__ W,
    const float* __restrict__ bias, float* __restrict__ C, int N, int K) {
    __shared__ float As[BK][BM];
    __shared__ float Bs[BK][BN];

    const int tid = threadIdx.x;
    const long m0 = (long)blockIdx.y * BM;
    const int n0 = blockIdx.x * BN;
    constexpr int TX = BN / TN;
    const int tx = tid % TX;
    const int ty = tid / TX;
    constexpr int NACC = TN / 2;

    unsigned long long acc[TM][NACC];
#pragma unroll
    for (int i = 0; i < TM; i++)
#pragma unroll
        for (int j = 0; j < NACC; j++) acc[i][j] = 0ull;

    constexpr int KC = BK / 4;
    constexpr int AR = (BM * KC) / NT;
    constexpr int BR = (BN * KC) / NT;

    int aRow[AR], aKc[AR];
#pragma unroll
    for (int r = 0; r < AR; r++) { int i = tid + r * NT; aRow[r] = i / KC; aKc[r] = (i % KC) * 4; }
    int bRow[BR], bKc[BR];
#pragma unroll
    for (int r = 0; r < BR; r++) { int i = tid + r * NT; bRow[r] = i / KC; bKc[r] = (i % KC) * 4; }

    float4 aReg[AR], bReg[BR];
#pragma unroll
    for (int r = 0; r < AR; r++)
        aReg[r] = *reinterpret_cast<const float4*>(A + (m0 + aRow[r]) * (long)K + aKc[r]);
#pragma unroll
    for (int r = 0; r < BR; r++)
        bReg[r] = *reinterpret_cast<const float4*>(W + (long)(n0 + bRow[r]) * K + bKc[r]);

    for (int k0 = 0; k0 < K; k0 += BK) {
#pragma unroll
        for (int r = 0; r < AR; r++) {
            float4 v = aReg[r];
            As[aKc[r] + 0][aRow[r]] = v.x; As[aKc[r] + 1][aRow[r]] = v.y;
            As[aKc[r] + 2][aRow[r]] = v.z; As[aKc[r] + 3][aRow[r]] = v.w;
        }
#pragma unroll
        for (int r = 0; r < BR; r++) {
            float4 v = bReg[r];
            Bs[bKc[r] + 0][bRow[r]] = v.x; Bs[bKc[r] + 1][bRow[r]] = v.y;
            Bs[bKc[r] + 2][bRow[r]] = v.z; Bs[bKc[r] + 3][bRow[r]] = v.w;
        }
        __syncthreads();

        int kn = k0 + BK;
        if (kn < K) {
#pragma unroll
            for (int r = 0; r < AR; r++)
                aReg[r] = *reinterpret_cast<const float4*>(A + (m0 + aRow[r]) * (long)K + kn + aKc[r]);
#pragma unroll
            for (int r = 0; r < BR; r++)
                bReg[r] = *reinterpret_cast<const float4*>(W + (long)(n0 + bRow[r]) * K + kn + bKc[r]);
        }

#pragma unroll
        for (int k = 0; k < BK; k++) {
            unsigned long long a2[TM];
#pragma unroll
            for (int i = 0; i < TM; i += 4) {
                float4 av = *reinterpret_cast<const float4*>(&As[k][ty * TM + i]);
                a2[i + 0] = pack2_dup(av.x); a2[i + 1] = pack2_dup(av.y);
                a2[i + 2] = pack2_dup(av.z); a2[i + 3] = pack2_dup(av.w);
            }
            unsigned long long b2[NACC];
#pragma unroll
            for (int j = 0; j < NACC; j += 2) {
                float4 bv = *reinterpret_cast<const float4*>(&Bs[k][tx * TN + 2 * j]);
                b2[j + 0] = pack2(bv.x, bv.y); b2[j + 1] = pack2(bv.z, bv.w);
            }
#pragma unroll
            for (int i = 0; i < TM; i++)
#pragma unroll
                for (int j = 0; j < NACC; j++) fma2(acc[i][j], a2[i], b2[j]);
        }
        __syncthreads();
    }

#pragma unroll
    for (int i = 0; i < TM; i++) {
        long m = m0 + ty * TM + i;
#pragma unroll
        for (int j = 0; j < NACC; j++) {
            int n = n0 + tx * TN + 2 * j;
            float2 v = unpack2(acc[i][j]);
            float v0 = v.x + bias[n];
            float v1 = v.y + bias[n + 1];
            v0 = v0 > 0.f ? v0 : ALPHA * v0;
            v1 = v1 > 0.f ? v1 : ALPHA * v1;
            float2 o; o.x = v0; o.y = v1;
            *reinterpret_cast<float2*>(C + m * (long)N + n) = o;
        }
    }
}

// ---------------- warp-per-row histogram entropy (no block barriers) ----------------
template <int D>
__global__ __launch_bounds__(256) void hist_entropy_warp_kernel(
    const float* __restrict__ Y, const float* __restrict__ clog,
    double* __restrict__ part) {
    constexpr int E = D / 32;                 // elems per lane (4 or 8)
    __shared__ int hist[8][D];
    const int lane = threadIdx.x & 31;
    const int w = threadIdx.x >> 5;
    const long row = (long)blockIdx.x * 8 + w;

    float v[E];
#pragma unroll
    for (int i = 0; i < E; i += 4) {
        float4 t = *reinterpret_cast<const float4*>(Y + row * D + lane * E + i);
        v[i] = t.x; v[i + 1] = t.y; v[i + 2] = t.z; v[i + 3] = t.w;
    }

    float mn = v[0], mx = v[0];
#pragma unroll
    for (int i = 1; i < E; i++) { mn = fminf(mn, v[i]); mx = fmaxf(mx, v[i]); }
#pragma unroll
    for (int o = 16; o > 0; o >>= 1) {
        mn = fminf(mn, __shfl_xor_sync(0xffffffffu, mn, o));
        mx = fmaxf(mx, __shfl_xor_sync(0xffffffffu, mx, o));
    }

#pragma unroll
    for (int i = 0; i < E; i++) hist[w][lane * E + i] = 0;
    __syncwarp();

    float width = mx - mn;
    float wsafe = width > 0.f ? width : 1.0f;
#pragma unroll
    for (int i = 0; i < E; i++) {
        float t = (v[i] - mn) / wsafe * (float)D;   // reference op order
        int b = (int)floorf(t);
        b = b < 0 ? 0 : (b > D - 1 ? D - 1 : b);
        unsigned mask = __match_any_sync(0xffffffffu, b);
        if ((__ffs(mask) - 1) == lane) atomicAdd(&hist[w][b], __popc(mask));
    }
    __syncwarp();

    float s = 0.f;
#pragma unroll
    for (int i = 0; i < E; i++) s += clog[hist[w][lane * E + i]];
#pragma unroll
    for (int o = 16; o > 0; o >>= 1) s += __shfl_xor_sync(0xffffffffu, s, o);
    if (lane == 0) {
        float H = 2.0f * logf((float)D) - s / (float)D;
        atomicAdd(&part[row & 1023], (double)H);
    }
}

__global__ __launch_bounds__(256) void hist_entropy32_kernel(const float* __restrict__ Y,
                                                             const float* __restrict__ logt,
                                                             double* __restrict__ part) {
    const int lane = threadIdx.x & 31;
    const int warp = threadIdx.x >> 5;
    const long row = (long)blockIdx.x * 8 + warp;
    float v = Y[row * 32 + lane];
    float mn = v, mx = v;
#pragma unroll
    for (int o = 16; o > 0; o >>= 1) {
        mn = fminf(mn, __shfl_xor_sync(0xffffffffu, mn, o));
        mx = fmaxf(mx, __shfl_xor_sync(0xffffffffu, mx, o));
    }
    float width = mx - mn;
    float wsafe = width > 0.f ? width : 1.0f;
    float t = (v - mn) / wsafe * 32.0f;
    int b = (int)floorf(t);
    b = b < 0 ? 0 : (b > 31 ? 31 : b);
    unsigned mask = __match_any_sync(0xffffffffu, b);
    int cnt = __popc(mask);
    float s = logt[cnt];
#pragma unroll
    for (int o = 16; o > 0; o >>= 1) s += __shfl_xor_sync(0xffffffffu, s, o);
    if (lane == 0) {
        float H = 2.0f * logf(32.0f) - s * (1.0f / 32.0f);
        atomicAdd(&part[row & 1023], (double)H);
    }
}

// ---------------- final layer: relu(y5 @ W6^T + b6) -> log_softmax ----------------
__global__ __launch_bounds__(256) void final_kernel(const float* __restrict__ Y5,
                                                    const float* __restrict__ W6,
                                                    const float* __restrict__ b6,
                                                    float* __restrict__ out) {
    __shared__ float w[320];
    __shared__ float bb[16];
    int tid = threadIdx.x;
    for (int i = tid; i < 320; i += 256) w[i] = W6[i];
    if (tid < 10) bb[tid] = b6[tid];
    __syncthreads();

    long row = (long)blockIdx.x * 256 + tid;
    float y[32];
    const float4* yp = reinterpret_cast<const float4*>(Y5 + row * 32);
#pragma unroll
    for (int i = 0; i < 8; i++) {
        float4 v = yp[i];
        y[4 * i] = v.x; y[4 * i + 1] = v.y; y[4 * i + 2] = v.z; y[4 * i + 3] = v.w;
    }
    float z[10];
#pragma unroll
    for (int j = 0; j < 10; j++) {
        float s = bb[j];
#pragma unroll
        for (int k = 0; k < 32; k++) s = fmaf(y[k], w[j * 32 + k], s);
        z[j] = s > 0.f ? s : 0.f;
    }
    float m = z[0];
#pragma unroll
    for (int j = 1; j < 10; j++) m = fmaxf(m, z[j]);
    float se = 0.f;
#pragma unroll
    for (int j = 0; j < 10; j++) se += expf(z[j] - m);
    float l = logf(se);
#pragma unroll
    for (int j = 0; j < 10; j++) out[row * 10 + j] = z[j] - m - l;
}

// ---------------- init: zero partials + fill log tables ----------------
__global__ void init_kernel() {
    int i = blockIdx.x * blockDim.x + threadIdx.x;
    if (i < 5 * 1024) g_part[i] = 0.0;
    if (i < 257) {
        float fi = (float)i;
        g_clog[i] = i > 0 ? fi * logf(fi) : 0.f;
        g_logt[i] = i > 0 ? logf(fi) : 0.f;
    }
}

__global__ __launch_bounds__(256) void finish_kernel(const double* __restrict__ part,
                                                     float* __restrict__ outH) {
    __shared__ double s[256];
    int layer = blockIdx.x;
    double a = 0.0;
    for (int i = threadIdx.x; i < 1024; i += 256) a += part[layer * 1024 + i];
    s[threadIdx.x] = a;
    __syncthreads();
    for (int o = 128; o > 0; o >>= 1) {
        if (threadIdx.x < o) s[threadIdx.x] += s[threadIdx.x + o];
        __syncthreads();
    }
    if (threadIdx.x == 0) outH[layer] = (float)(s[0] / 65536.0);
}

// ---------------- launch: hist chain forked onto a side stream (graph fork-join) ----------------
extern "C" void kernel_launch(void* const* d_in, const int* in_sizes, int n_in,
                              void* d_out, int out_size) {
    (void)in_sizes; (void)n_in;
    const float* x  = (const float*)d_in[0];
    const float* W1 = (const float*)d_in[1];
    const float* b1 = (const float*)d_in[2];
    const float* W2 = (const float*)d_in[3];
    const float* b2 = (const float*)d_in[4];
    const float* W3 = (const float*)d_in[5];
    const float* b3 = (const float*)d_in[6];
    const float* W4 = (const float*)d_in[7];
    const float* b4 = (const float*)d_in[8];
    const float* W5 = (const float*)d_in[9];
    const float* b5 = (const float*)d_in[10];
    const float* W6 = (const float*)d_in[11];
    const float* b6 = (const float*)d_in[12];
    float* out = (float*)d_out;
    float* outH = out + (out_size - 5);

    float *y1, *y2, *y3, *y4, *y5, *clog, *logt;
    double* part;
    cudaGetSymbolAddress((void**)&y1, g_y1);
    cudaGetSymbolAddress((void**)&y2, g_y2);
    cudaGetSymbolAddress((void**)&y3, g_y3);
    cudaGetSymbolAddress((void**)&y4, g_y4);
    cudaGetSymbolAddress((void**)&y5, g_y5);
    cudaGetSymbolAddress((void**)&part, g_part);
    cudaGetSymbolAddress((void**)&clog, g_clog);
    cudaGetSymbolAddress((void**)&logt, g_logt);

    // one-time host resources (streams/events are host objects, not device memory)
    static cudaStream_t s2 = nullptr;
    static cudaEvent_t eL1, eL2, eL3, eL4, eL5, eH;
    if (!s2) {
        cudaStreamCreateWithFlags(&s2, cudaStreamNonBlocking);
        cudaEventCreateWithFlags(&eL1, cudaEventDisableTiming);
        cudaEventCreateWithFlags(&eL2, cudaEventDisableTiming);
        cudaEventCreateWithFlags(&eL3, cudaEventDisableTiming);
        cudaEventCreateWithFlags(&eL4, cudaEventDisableTiming);
        cudaEventCreateWithFlags(&eL5, cudaEventDisableTiming);
        cudaEventCreateWithFlags(&eH, cudaEventDisableTiming);
    }

    init_kernel<<<20, 256>>>();

    // L1 (main)
    hmma_gemm_kernel<256, 784><<<dim3(2, BATCH / 128), 256>>>(x, W1, b1, y1);
    cudaEventRecord(eL1, 0);
    cudaStreamWaitEvent(s2, eL1, 0);
    hist_entropy_warp_kernel<256><<<BATCH / 8, 256, 0, s2>>>(y1, clog, part + 0 * 1024);

    // L2 (main) overlaps hist1 (s2)
    hmma_gemm_kernel<128, 256><<<dim3(1, BATCH / 128), 256>>>(y1, W2, b2, y2);
    cudaEventRecord(eL2, 0);
    cudaStreamWaitEvent(s2, eL2, 0);
    hist_entropy_warp_kernel<128><<<BATCH / 8, 256, 0, s2>>>(y2, clog, part + 1 * 1024);

    // L3
    hmma_gemm_kernel<128, 128><<<dim3(1, BATCH / 128), 256>>>(y2, W3, b3, y3);
    cudaEventRecord(eL3, 0);
    cudaStreamWaitEvent(s2, eL3, 0);
    hist_entropy_warp_kernel<128><<<BATCH / 8, 256, 0, s2>>>(y3, clog, part + 2 * 1024);

    // L4
    hmma_gemm_kernel<128, 128><<<dim3(1, BATCH / 128), 256>>>(y3, W4, b4, y4);
    cudaEventRecord(eL4, 0);
    cudaStreamWaitEvent(s2, eL4, 0);
    hist_entropy_warp_kernel<128><<<BATCH / 8, 256, 0, s2>>>(y4, clog, part + 3 * 1024);

    // L5 (main)
    gemm_lrelu_kernel<128, 32, 16, 8, 4, 128>
        <<<dim3(1, BATCH / 128), 128>>>(y4, W5, b5, y5, 32, 128);
    cudaEventRecord(eL5, 0);
    cudaStreamWaitEvent(s2, eL5, 0);
    hist_entropy32_kernel<<<BATCH / 8, 256, 0, s2>>>(y5, logt, part + 4 * 1024);
    cudaEventRecord(eH, s2);

    // L6 + log_softmax (main, needs only y5)
    final_kernel<<<BATCH / 256, 256>>>(y5, W6, b6, out);

    // join: entropy means need all hists
    cudaStreamWaitEvent(0, eH, 0);
    finish_kernel<<<5, 256>>>(part, outH);
}